// round 13
// baseline (speedup 1.0000x reference)
#include <cuda_runtime.h>
#include <cuda_fp16.h>
#include <math.h>
#include <stdint.h>

#define NN 8192
#define DD 64
#define NSPLIT 8
#define MT 128          // rows per CTA
#define JT 128          // j tile
#define JSPAN (NN / NSPLIT)        // 1024 j's per CTA
#define NTILE (JSPAN / JT)         // 8 j-tiles per CTA
#define SGS 136         // padded sG row stride (halves)

// ---- static device scratch (no allocation allowed) ----
__device__ float  g_G[NN * DD];            // G = relu(X@W+b)@wt (fp32, row-major)
__device__ __half g_GT[DD * NN];           // G transposed, fp16 (feature-major)
__device__ float  g_V[NN * DD];            // layer-1 output
__device__ float  g_num[NSPLIT * NN * DD]; // numerator partials
__device__ float  g_den[NSPLIT * NN];      // denominator partials (pass1 only)
__device__ __half g_ephe[NN];              // scaled eta (fp16)
__device__ __half g_ephp[NN];              // scaled phi (fp16)
__device__ float  g_part[64 * 64];

// ============================================================
// ep: scaled fp16 SoA coords.  s = sqrt(alpha*log2e) so that
// 2^(-(de^2+dp^2)) == exp(-alpha*dR^2)
// ============================================================
__global__ void ep_kernel(const float* __restrict__ x, const float* __restrict__ alpha) {
    const float LOG2E = 1.44269504088896340736f;
    float s = sqrtf(alpha[0] * LOG2E);
    int j = blockIdx.x * 256 + threadIdx.x;
    g_ephe[j] = __float2half(x[j * 7 + 1] * s);
    g_ephp[j] = __float2half(x[j * 7 + 2] * s);
}

// ============================================================
// prep v2: G = relu(X@W+b)@wt, weights in SMEM, 4 cols/thread via
// float4 LDS. 16 row-slots x 16 col-groups, 32 rows/CTA, low regs.
// ============================================================
template<int DIN>
__global__ __launch_bounds__(256) void prep_kernel(
    const float* __restrict__ Xext, const float* __restrict__ W,
    const float* __restrict__ b, const float* __restrict__ wt)
{
    __shared__ float sW[DIN * 64];
    __shared__ float swt[64 * 64];
    __shared__ float sx[16][(DIN <= 8) ? 8 : 64];
    __shared__ float sh[16][64];
    __shared__ __half sgt[32][64];

    const int tid = threadIdx.x;
    const int rs = tid >> 4;       // row slot 0..15
    const int cg = tid & 15;       // col group (4 cols)
    const float* X = Xext ? Xext : g_V;
    const int rowbase = blockIdx.x * 32;

    // cooperative weight loads (float4)
    for (int t = tid; t < DIN * 16; t += 256)
        ((float4*)sW)[t] = ((const float4*)W)[t];
    for (int t = tid; t < 64 * 16; t += 256)
        ((float4*)swt)[t] = ((const float4*)wt)[t];
    const float4 bk4 = *(const float4*)&b[cg * 4];
    __syncthreads();

    #pragma unroll
    for (int half = 0; half < 2; half++) {
        const int row = rowbase + half * 16 + rs;
        // load X row into sx
        if (DIN <= 8) {
            if (cg < DIN) sx[rs][cg] = X[row * DIN + cg];
        } else {
            *(float4*)&sx[rs][cg * 4] = *(const float4*)&X[row * DIN + cg * 4];
        }
        __syncthreads();
        // stage 1: h = relu(x @ W + b), 4 cols per thread
        float a0 = bk4.x, a1 = bk4.y, a2 = bk4.z, a3 = bk4.w;
        #pragma unroll
        for (int d = 0; d < DIN; d++) {
            float xv = sx[rs][d];
            float4 w4 = *(const float4*)&sW[d * 64 + cg * 4];
            a0 = fmaf(xv, w4.x, a0); a1 = fmaf(xv, w4.y, a1);
            a2 = fmaf(xv, w4.z, a2); a3 = fmaf(xv, w4.w, a3);
        }
        *(float4*)&sh[rs][cg * 4] = make_float4(fmaxf(a0, 0.f), fmaxf(a1, 0.f),
                                                fmaxf(a2, 0.f), fmaxf(a3, 0.f));
        __syncthreads();
        // stage 2: g = h @ wt, 4 cols per thread
        float g0 = 0.f, g1 = 0.f, g2 = 0.f, g3 = 0.f;
        #pragma unroll
        for (int m = 0; m < 64; m++) {
            float hv = sh[rs][m];
            float4 w4 = *(const float4*)&swt[m * 64 + cg * 4];
            g0 = fmaf(hv, w4.x, g0); g1 = fmaf(hv, w4.y, g1);
            g2 = fmaf(hv, w4.z, g2); g3 = fmaf(hv, w4.w, g3);
        }
        *(float4*)&g_G[row * 64 + cg * 4] = make_float4(g0, g1, g2, g3);
        sgt[half * 16 + rs][cg * 4 + 0] = __float2half(g0);
        sgt[half * 16 + rs][cg * 4 + 1] = __float2half(g1);
        sgt[half * 16 + rs][cg * 4 + 2] = __float2half(g2);
        sgt[half * 16 + rs][cg * 4 + 3] = __float2half(g3);
    }
    __syncthreads();
    // coalesced transposed store: g_GT[k][rowbase..rowbase+31]
    const int kk = tid >> 2, seg = tid & 3;
    __half tmp[8];
    #pragma unroll
    for (int r = 0; r < 8; r++) tmp[r] = sgt[seg * 8 + r][kk];
    *(float4*)(g_GT + kk * NN + rowbase + seg * 8) = *(float4*)tmp;
}

// ============================================================
// wgen: half2-packed weights for a j-pair.
// drn = LL - de^2 - dp^2 ; w = 2^(2^drn) = exp(exp(-alpha dR^2))
// ============================================================
__device__ __forceinline__ uint32_t wgen(half2 ei, half2 pi, half2 ej, half2 pj,
                                         half2 tps2, half2 LL2) {
    half2 de = __hsub2(ei, ej);
    half2 d  = __hsub2(pi, pj);
    half2 ad = __habs2(d);
    half2 dp = __hmin2(ad, __hsub2(tps2, ad));
    half2 s  = __hfma2(dp, dp, __hmul2(de, de));
    half2 drn = __hsub2(LL2, s);
    uint32_t r;
    asm("{\n\t.reg .b32 t;\n\t"
        "ex2.approx.f16x2 t, %1;\n\t"
        "ex2.approx.f16x2 %0, t;\n\t}"
        : "=r"(r) : "r"(*(uint32_t*)&drn));
    return r;
}

// ============================================================
// pass: S@G on HMMA. Weights recomputed on the fly in BOTH layers.
// DEN=1 additionally accumulates the softmax denominator via an
// extra MMA against a constant ones-B fragment (layer 1 only).
// ============================================================
template<int DEN>
__global__ __launch_bounds__(256, 3) void pass_kernel(const float* __restrict__ alpha)
{
    __shared__ __half sG[64 * SGS];   // [feature][j] padded
    __shared__ __half sEe[JT];
    __shared__ __half sEp[JT];

    const int tid = threadIdx.x;
    const int warp = tid >> 5, lane = tid & 31;
    const int gid = lane >> 2, tig = lane & 3;
    const int rowtile = blockIdx.x, jsplit = blockIdx.y;
    const int j0base = jsplit * JSPAN;

    const int row0 = rowtile * MT + warp * 16 + gid;

    const float LOG2E = 1.44269504088896340736f;
    const float TWOPI = 6.28318530717958647692f;
    float tps = TWOPI * sqrtf(alpha[0] * LOG2E);
    const half2 tps2 = __half2half2(__float2half(tps));
    const half2 LL2  = __half2half2(__float2half(0.52876637294489770f));
    const half2 ei0_2 = __half2half2(g_ephe[row0]);
    const half2 pi0_2 = __half2half2(g_ephp[row0]);
    const half2 ei1_2 = __half2half2(g_ephe[row0 + 8]);
    const half2 pi1_2 = __half2half2(g_ephp[row0 + 8]);

    // ldmatrix per-lane address offset (halves)
    const int m = lane >> 3;
    const int bro = ((m >> 1) * 8 + (lane & 7)) * SGS + (m & 1) * 8;

    uint32_t sgb;
    asm("{ .reg .u64 t; cvta.to.shared.u64 t, %1; cvt.u32.u64 %0, t; }" : "=r"(sgb) : "l"(sG));

    float acc[8][4];
    #pragma unroll
    for (int nt = 0; nt < 8; nt++)
        #pragma unroll
        for (int q = 0; q < 4; q++) acc[nt][q] = 0.f;
    float accd[4] = {0.f, 0.f, 0.f, 0.f};   // den accumulator (DEN only)

    for (int t = 0; t < NTILE; t++) {
        const int j0 = j0base + t * JT;
        __syncthreads();
        #pragma unroll
        for (int i = 0; i < 4; i++) {
            int idx = tid + i * 256;
            int f = idx >> 4, c = idx & 15;
            *(float4*)(sG + f * SGS + c * 8) = *(const float4*)(g_GT + f * NN + j0 + c * 8);
        }
        if (tid < 32) {
            if (tid < 16)
                *(uint4*)(sEe + tid * 8) = *(const uint4*)(g_ephe + j0 + tid * 8);
            else
                *(uint4*)(sEp + (tid - 16) * 8) = *(const uint4*)(g_ephp + j0 + (tid - 16) * 8);
        }
        __syncthreads();

        #pragma unroll
        for (int ks = 0; ks < 8; ks++) {
            const int jj = ks * 16;
            half2 ej0 = *(const half2*)(sEe + jj + tig * 2);
            half2 pj0 = *(const half2*)(sEp + jj + tig * 2);
            half2 ej1 = *(const half2*)(sEe + jj + 8 + tig * 2);
            half2 pj1 = *(const half2*)(sEp + jj + 8 + tig * 2);
            uint32_t af0 = wgen(ei0_2, pi0_2, ej0, pj0, tps2, LL2);
            uint32_t af1 = wgen(ei1_2, pi1_2, ej0, pj0, tps2, LL2);
            uint32_t af2 = wgen(ei0_2, pi0_2, ej1, pj1, tps2, LL2);
            uint32_t af3 = wgen(ei1_2, pi1_2, ej1, pj1, tps2, LL2);
            if (DEN) {
                // den: MMA against constant all-ones B fragment
                asm volatile(
                    "mma.sync.aligned.m16n8k16.row.col.f32.f16.f16.f32 "
                    "{%0,%1,%2,%3}, {%4,%5,%6,%7}, {%8,%8}, {%0,%1,%2,%3};"
                    : "+f"(accd[0]), "+f"(accd[1]), "+f"(accd[2]), "+f"(accd[3])
                    : "r"(af0), "r"(af1), "r"(af2), "r"(af3), "r"(0x3C003C00u));
            }

            // two half-groups of (2 ldmatrix.x4 + 4 MMA) to cap live regs
            #pragma unroll
            for (int h = 0; h < 2; h++) {
                uint32_t bf[4][2];
                #pragma unroll
                for (int q = 0; q < 2; q++) {
                    uint32_t addr = sgb + (uint32_t)((h * 2 + q) * 16 * SGS + bro + jj) * 2u;
                    asm volatile("ldmatrix.sync.aligned.m8n8.x4.shared.b16 {%0,%1,%2,%3}, [%4];"
                        : "=r"(bf[2 * q][0]), "=r"(bf[2 * q][1]),
                          "=r"(bf[2 * q + 1][0]), "=r"(bf[2 * q + 1][1])
                        : "r"(addr));
                }
                #pragma unroll
                for (int nt = 0; nt < 4; nt++) {
                    asm volatile(
                        "mma.sync.aligned.m16n8k16.row.col.f32.f16.f16.f32 "
                        "{%0,%1,%2,%3}, {%4,%5,%6,%7}, {%8,%9}, {%0,%1,%2,%3};"
                        : "+f"(acc[h * 4 + nt][0]), "+f"(acc[h * 4 + nt][1]),
                          "+f"(acc[h * 4 + nt][2]), "+f"(acc[h * 4 + nt][3])
                        : "r"(af0), "r"(af1), "r"(af2), "r"(af3),
                          "r"(bf[nt][0]), "r"(bf[nt][1]));
                }
            }
        }
    }

    if (DEN && tig == 0) {
        g_den[jsplit * NN + row0] = accd[0];
        g_den[jsplit * NN + row0 + 8] = accd[2];
    }

    float* np = g_num + (size_t)jsplit * NN * DD;
    #pragma unroll
    for (int nt = 0; nt < 8; nt++) {
        *(float2*)(np + (size_t)row0 * DD + nt * 8 + tig * 2) =
            make_float2(acc[nt][0], acc[nt][1]);
        *(float2*)(np + (size_t)(row0 + 8) * DD + nt * 8 + tig * 2) =
            make_float2(acc[nt][2], acc[nt][3]);
    }
}

// ============================================================
// finalize (layer 1): V = relu(num/den + G + bs)
// ============================================================
__global__ __launch_bounds__(256) void finalize_kernel(const float* __restrict__ bs)
{
    int gid = blockIdx.x * 256 + threadIdx.x;
    int i = gid >> 6;
    float ds = 0.f, ns = 0.f;
    #pragma unroll
    for (int s = 0; s < NSPLIT; s++) {
        ds += g_den[s * NN + i];
        ns += g_num[(size_t)s * NN * DD + gid];
    }
    float v = ns / ds + g_G[gid] + bs[0];
    g_V[gid] = fmaxf(v, 0.f);
}

// ============================================================
// reduce (finalize2 fused): column sums of relu(num/den + G + bs)
// ============================================================
__global__ __launch_bounds__(256) void reduce_kernel(const float* __restrict__ bs)
{
    __shared__ float s[4][64];
    int tid = threadIdx.x;
    int k = tid & 63;
    int rg = tid >> 6;
    int bkt = blockIdx.x;
    float acc = 0.f;
    for (int r = rg; r < 128; r += 4) {
        int row = bkt * 128 + r;
        float ds = 0.f, ns = 0.f;
        #pragma unroll
        for (int sp = 0; sp < NSPLIT; sp++) {
            ds += g_den[sp * NN + row];
            ns += g_num[(size_t)sp * NN * DD + (size_t)row * DD + k];
        }
        float v = ns / ds + g_G[row * 64 + k] + bs[0];
        acc += fmaxf(v, 0.f);
    }
    s[rg][k] = acc;
    __syncthreads();
    if (tid < 64)
        g_part[bkt * 64 + tid] = s[0][tid] + s[1][tid] + s[2][tid] + s[3][tid];
}

__global__ void head_kernel(const float* __restrict__ Wl,
                            const float* __restrict__ bl,
                            float* __restrict__ out)
{
    __shared__ float sv[64];
    int t = threadIdx.x;
    float sk = 0.f;
    for (int b = 0; b < 64; b++) sk += g_part[b * 64 + t];
    sv[t] = sk * Wl[t];
    __syncthreads();
    if (t == 0) {
        float s = 0.f;
        for (int i = 0; i < 64; i++) s += sv[i];
        s += bl[0];
        out[0] = 1.f / (1.f + expf(-s));
    }
}

extern "C" void kernel_launch(void* const* d_in, const int* in_sizes, int n_in,
                              void* d_out, int out_size)
{
    const float* x     = (const float*)d_in[0];
    const float* alpha = (const float*)d_in[1];
    const float* W1    = (const float*)d_in[2];
    const float* b1    = (const float*)d_in[3];
    const float* wt1   = (const float*)d_in[4];
    const float* bs1   = (const float*)d_in[5];
    const float* W2    = (const float*)d_in[6];
    const float* b2    = (const float*)d_in[7];
    const float* wt2   = (const float*)d_in[8];
    const float* bs2   = (const float*)d_in[9];
    const float* Wl    = (const float*)d_in[10];
    const float* bl    = (const float*)d_in[11];
    float* out = (float*)d_out;

    dim3 pg(NN / MT, NSPLIT);

    ep_kernel<<<NN / 256, 256>>>(x, alpha);
    // layer 1: weights on the fly, den accumulated
    prep_kernel<7><<<NN / 32, 256>>>(x, W1, b1, wt1);
    pass_kernel<1><<<pg, 256>>>(alpha);
    finalize_kernel<<<NN * DD / 256, 256>>>(bs1);
    // layer 2: weights recomputed on the fly, den reused from layer 1
    prep_kernel<64><<<NN / 32, 256>>>(nullptr, W2, b2, wt2);
    pass_kernel<0><<<pg, 256>>>(alpha);
    // head: finalize2 fused into reduce
    reduce_kernel<<<64, 256>>>(bs2);
    head_kernel<<<1, 64>>>(Wl, bl, out);
}

// round 14
// speedup vs baseline: 1.0141x; 1.0141x over previous
#include <cuda_runtime.h>
#include <cuda_fp16.h>
#include <math.h>
#include <stdint.h>

#define NN 8192
#define DD 64
#define NSPLIT 4
#define MT 128          // rows per CTA
#define JT 128          // j tile
#define JSPAN (NN / NSPLIT)        // 2048 j's per CTA
#define NTILE (JSPAN / JT)         // 16 j-tiles per CTA
#define SGS 136         // padded sG row stride (halves)

// ---- static device scratch (no allocation allowed) ----
__device__ float  g_G[NN * DD];            // G = relu(X@W+b)@wt (fp32, row-major)
__device__ __half g_GT[DD * NN];           // G transposed, fp16 (feature-major)
__device__ float  g_V[NN * DD];            // layer-1 output
__device__ float  g_num[NSPLIT * NN * DD]; // numerator partials
__device__ float  g_den[NSPLIT * NN];      // denominator partials (pass1 only)
__device__ __half g_ephe[NN];              // scaled eta (fp16)
__device__ __half g_ephp[NN];              // scaled phi (fp16)
__device__ float  g_part[64 * 64];

// ============================================================
// ep: scaled fp16 SoA coords.  s = sqrt(alpha*log2e) so that
// 2^(-(de^2+dp^2)) == exp(-alpha*dR^2)
// ============================================================
__global__ void ep_kernel(const float* __restrict__ x, const float* __restrict__ alpha) {
    const float LOG2E = 1.44269504088896340736f;
    float s = sqrtf(alpha[0] * LOG2E);
    int j = blockIdx.x * 256 + threadIdx.x;
    g_ephe[j] = __float2half(x[j * 7 + 1] * s);
    g_ephp[j] = __float2half(x[j * 7 + 2] * s);
}

// ============================================================
// prep v2: G = relu(X@W+b)@wt, weights in SMEM, 4 cols/thread via
// float4 LDS. 16 row-slots x 16 col-groups, 32 rows/CTA, low regs.
// ============================================================
template<int DIN>
__global__ __launch_bounds__(256) void prep_kernel(
    const float* __restrict__ Xext, const float* __restrict__ W,
    const float* __restrict__ b, const float* __restrict__ wt)
{
    __shared__ float sW[DIN * 64];
    __shared__ float swt[64 * 64];
    __shared__ float sx[16][(DIN <= 8) ? 8 : 64];
    __shared__ float sh[16][64];
    __shared__ __half sgt[32][64];

    const int tid = threadIdx.x;
    const int rs = tid >> 4;       // row slot 0..15
    const int cg = tid & 15;       // col group (4 cols)
    const float* X = Xext ? Xext : g_V;
    const int rowbase = blockIdx.x * 32;

    // cooperative weight loads (float4)
    for (int t = tid; t < DIN * 16; t += 256)
        ((float4*)sW)[t] = ((const float4*)W)[t];
    for (int t = tid; t < 64 * 16; t += 256)
        ((float4*)swt)[t] = ((const float4*)wt)[t];
    const float4 bk4 = *(const float4*)&b[cg * 4];
    __syncthreads();

    #pragma unroll
    for (int half = 0; half < 2; half++) {
        const int row = rowbase + half * 16 + rs;
        // load X row into sx
        if (DIN <= 8) {
            if (cg < DIN) sx[rs][cg] = X[row * DIN + cg];
        } else {
            *(float4*)&sx[rs][cg * 4] = *(const float4*)&X[row * DIN + cg * 4];
        }
        __syncthreads();
        // stage 1: h = relu(x @ W + b), 4 cols per thread
        float a0 = bk4.x, a1 = bk4.y, a2 = bk4.z, a3 = bk4.w;
        #pragma unroll
        for (int d = 0; d < DIN; d++) {
            float xv = sx[rs][d];
            float4 w4 = *(const float4*)&sW[d * 64 + cg * 4];
            a0 = fmaf(xv, w4.x, a0); a1 = fmaf(xv, w4.y, a1);
            a2 = fmaf(xv, w4.z, a2); a3 = fmaf(xv, w4.w, a3);
        }
        *(float4*)&sh[rs][cg * 4] = make_float4(fmaxf(a0, 0.f), fmaxf(a1, 0.f),
                                                fmaxf(a2, 0.f), fmaxf(a3, 0.f));
        __syncthreads();
        // stage 2: g = h @ wt, 4 cols per thread
        float g0 = 0.f, g1 = 0.f, g2 = 0.f, g3 = 0.f;
        #pragma unroll
        for (int m = 0; m < 64; m++) {
            float hv = sh[rs][m];
            float4 w4 = *(const float4*)&swt[m * 64 + cg * 4];
            g0 = fmaf(hv, w4.x, g0); g1 = fmaf(hv, w4.y, g1);
            g2 = fmaf(hv, w4.z, g2); g3 = fmaf(hv, w4.w, g3);
        }
        *(float4*)&g_G[row * 64 + cg * 4] = make_float4(g0, g1, g2, g3);
        sgt[half * 16 + rs][cg * 4 + 0] = __float2half(g0);
        sgt[half * 16 + rs][cg * 4 + 1] = __float2half(g1);
        sgt[half * 16 + rs][cg * 4 + 2] = __float2half(g2);
        sgt[half * 16 + rs][cg * 4 + 3] = __float2half(g3);
    }
    __syncthreads();
    // coalesced transposed store: g_GT[k][rowbase..rowbase+31]
    const int kk = tid >> 2, seg = tid & 3;
    __half tmp[8];
    #pragma unroll
    for (int r = 0; r < 8; r++) tmp[r] = sgt[seg * 8 + r][kk];
    *(float4*)(g_GT + kk * NN + rowbase + seg * 8) = *(float4*)tmp;
}

// ============================================================
// wgen: half2-packed weights for a j-pair.
// u = 2^(-(de^2+dp^2)) = exp(-alpha dR^2)  (one MUFU ex2)
// w = e^u via degree-5 Taylor at u=0.5 (coeffs * e^0.5) — no 2nd MUFU.
// ============================================================
__device__ __forceinline__ uint32_t wgen(half2 ei, half2 pi, half2 ej, half2 pj,
                                         half2 tps2) {
    const half2 C0 = __half2half2(__float2half(1.64872127f));   // E
    const half2 C1 = __half2half2(__float2half(1.64872127f));   // E
    const half2 C2 = __half2half2(__float2half(0.82436064f));   // E/2
    const half2 C3 = __half2half2(__float2half(0.27478688f));   // E/6
    const half2 C4 = __half2half2(__float2half(0.06869672f));   // E/24
    const half2 C5 = __half2half2(__float2half(0.013739344f));  // E/120
    const half2 H  = __half2half2(__float2half(0.5f));

    half2 de = __hsub2(ei, ej);
    half2 d  = __hsub2(pi, pj);
    half2 ad = __habs2(d);
    half2 dp = __hmin2(ad, __hsub2(tps2, ad));
    half2 s  = __hfma2(dp, dp, __hmul2(de, de));
    half2 ns = __hneg2(s);
    uint32_t u;
    asm("ex2.approx.f16x2 %0, %1;" : "=r"(u) : "r"(*(uint32_t*)&ns));
    half2 uh = *(half2*)&u;
    half2 t = __hsub2(uh, H);
    half2 q = __hfma2(t, C5, C4);
    q = __hfma2(t, q, C3);
    q = __hfma2(t, q, C2);
    q = __hfma2(t, q, C1);
    q = __hfma2(t, q, C0);
    return *(uint32_t*)&q;
}

// ============================================================
// pass: S@G on HMMA. Weights recomputed on the fly in BOTH layers.
// DEN=1 additionally accumulates the softmax denominator via an
// extra MMA against a constant ones-B fragment (layer 1 only).
// ============================================================
template<int DEN>
__global__ __launch_bounds__(256, 3) void pass_kernel(const float* __restrict__ alpha)
{
    __shared__ __half sG[64 * SGS];   // [feature][j] padded
    __shared__ __half sEe[JT];
    __shared__ __half sEp[JT];

    const int tid = threadIdx.x;
    const int warp = tid >> 5, lane = tid & 31;
    const int gid = lane >> 2, tig = lane & 3;
    const int rowtile = blockIdx.x, jsplit = blockIdx.y;
    const int j0base = jsplit * JSPAN;

    const int row0 = rowtile * MT + warp * 16 + gid;

    const float LOG2E = 1.44269504088896340736f;
    const float TWOPI = 6.28318530717958647692f;
    float tps = TWOPI * sqrtf(alpha[0] * LOG2E);
    const half2 tps2 = __half2half2(__float2half(tps));
    const half2 ei0_2 = __half2half2(g_ephe[row0]);
    const half2 pi0_2 = __half2half2(g_ephp[row0]);
    const half2 ei1_2 = __half2half2(g_ephe[row0 + 8]);
    const half2 pi1_2 = __half2half2(g_ephp[row0 + 8]);

    // ldmatrix per-lane address offset (halves)
    const int m = lane >> 3;
    const int bro = ((m >> 1) * 8 + (lane & 7)) * SGS + (m & 1) * 8;

    uint32_t sgb;
    asm("{ .reg .u64 t; cvta.to.shared.u64 t, %1; cvt.u32.u64 %0, t; }" : "=r"(sgb) : "l"(sG));

    float acc[8][4];
    #pragma unroll
    for (int nt = 0; nt < 8; nt++)
        #pragma unroll
        for (int q = 0; q < 4; q++) acc[nt][q] = 0.f;
    float accd[4] = {0.f, 0.f, 0.f, 0.f};   // den accumulator (DEN only)

    for (int t = 0; t < NTILE; t++) {
        const int j0 = j0base + t * JT;
        __syncthreads();
        #pragma unroll
        for (int i = 0; i < 4; i++) {
            int idx = tid + i * 256;
            int f = idx >> 4, c = idx & 15;
            *(float4*)(sG + f * SGS + c * 8) = *(const float4*)(g_GT + f * NN + j0 + c * 8);
        }
        if (tid < 32) {
            if (tid < 16)
                *(uint4*)(sEe + tid * 8) = *(const uint4*)(g_ephe + j0 + tid * 8);
            else
                *(uint4*)(sEp + (tid - 16) * 8) = *(const uint4*)(g_ephp + j0 + (tid - 16) * 8);
        }
        __syncthreads();

        #pragma unroll
        for (int ks = 0; ks < 8; ks++) {
            const int jj = ks * 16;
            half2 ej0 = *(const half2*)(sEe + jj + tig * 2);
            half2 pj0 = *(const half2*)(sEp + jj + tig * 2);
            half2 ej1 = *(const half2*)(sEe + jj + 8 + tig * 2);
            half2 pj1 = *(const half2*)(sEp + jj + 8 + tig * 2);
            uint32_t af0 = wgen(ei0_2, pi0_2, ej0, pj0, tps2);
            uint32_t af1 = wgen(ei1_2, pi1_2, ej0, pj0, tps2);
            uint32_t af2 = wgen(ei0_2, pi0_2, ej1, pj1, tps2);
            uint32_t af3 = wgen(ei1_2, pi1_2, ej1, pj1, tps2);
            if (DEN) {
                // den: MMA against constant all-ones B fragment
                asm volatile(
                    "mma.sync.aligned.m16n8k16.row.col.f32.f16.f16.f32 "
                    "{%0,%1,%2,%3}, {%4,%5,%6,%7}, {%8,%8}, {%0,%1,%2,%3};"
                    : "+f"(accd[0]), "+f"(accd[1]), "+f"(accd[2]), "+f"(accd[3])
                    : "r"(af0), "r"(af1), "r"(af2), "r"(af3), "r"(0x3C003C00u));
            }

            // two half-groups of (2 ldmatrix.x4 + 4 MMA) to cap live regs
            #pragma unroll
            for (int h = 0; h < 2; h++) {
                uint32_t bf[4][2];
                #pragma unroll
                for (int q = 0; q < 2; q++) {
                    uint32_t addr = sgb + (uint32_t)((h * 2 + q) * 16 * SGS + bro + jj) * 2u;
                    asm volatile("ldmatrix.sync.aligned.m8n8.x4.shared.b16 {%0,%1,%2,%3}, [%4];"
                        : "=r"(bf[2 * q][0]), "=r"(bf[2 * q][1]),
                          "=r"(bf[2 * q + 1][0]), "=r"(bf[2 * q + 1][1])
                        : "r"(addr));
                }
                #pragma unroll
                for (int nt = 0; nt < 4; nt++) {
                    asm volatile(
                        "mma.sync.aligned.m16n8k16.row.col.f32.f16.f16.f32 "
                        "{%0,%1,%2,%3}, {%4,%5,%6,%7}, {%8,%9}, {%0,%1,%2,%3};"
                        : "+f"(acc[h * 4 + nt][0]), "+f"(acc[h * 4 + nt][1]),
                          "+f"(acc[h * 4 + nt][2]), "+f"(acc[h * 4 + nt][3])
                        : "r"(af0), "r"(af1), "r"(af2), "r"(af3),
                          "r"(bf[nt][0]), "r"(bf[nt][1]));
                }
            }
        }
    }

    if (DEN && tig == 0) {
        g_den[jsplit * NN + row0] = accd[0];
        g_den[jsplit * NN + row0 + 8] = accd[2];
    }

    float* np = g_num + (size_t)jsplit * NN * DD;
    #pragma unroll
    for (int nt = 0; nt < 8; nt++) {
        *(float2*)(np + (size_t)row0 * DD + nt * 8 + tig * 2) =
            make_float2(acc[nt][0], acc[nt][1]);
        *(float2*)(np + (size_t)(row0 + 8) * DD + nt * 8 + tig * 2) =
            make_float2(acc[nt][2], acc[nt][3]);
    }
}

// ============================================================
// finalize (layer 1): V = relu(num/den + G + bs)
// ============================================================
__global__ __launch_bounds__(256) void finalize_kernel(const float* __restrict__ bs)
{
    int gid = blockIdx.x * 256 + threadIdx.x;
    int i = gid >> 6;
    float ds = 0.f, ns = 0.f;
    #pragma unroll
    for (int s = 0; s < NSPLIT; s++) {
        ds += g_den[s * NN + i];
        ns += g_num[(size_t)s * NN * DD + gid];
    }
    float v = ns / ds + g_G[gid] + bs[0];
    g_V[gid] = fmaxf(v, 0.f);
}

// ============================================================
// reduce (finalize2 fused): column sums of relu(num/den + G + bs)
// ============================================================
__global__ __launch_bounds__(256) void reduce_kernel(const float* __restrict__ bs)
{
    __shared__ float s[4][64];
    int tid = threadIdx.x;
    int k = tid & 63;
    int rg = tid >> 6;
    int bkt = blockIdx.x;
    float acc = 0.f;
    for (int r = rg; r < 128; r += 4) {
        int row = bkt * 128 + r;
        float ds = 0.f, ns = 0.f;
        #pragma unroll
        for (int sp = 0; sp < NSPLIT; sp++) {
            ds += g_den[sp * NN + row];
            ns += g_num[(size_t)sp * NN * DD + (size_t)row * DD + k];
        }
        float v = ns / ds + g_G[row * 64 + k] + bs[0];
        acc += fmaxf(v, 0.f);
    }
    s[rg][k] = acc;
    __syncthreads();
    if (tid < 64)
        g_part[bkt * 64 + tid] = s[0][tid] + s[1][tid] + s[2][tid] + s[3][tid];
}

__global__ void head_kernel(const float* __restrict__ Wl,
                            const float* __restrict__ bl,
                            float* __restrict__ out)
{
    __shared__ float sv[64];
    int t = threadIdx.x;
    float sk = 0.f;
    for (int b = 0; b < 64; b++) sk += g_part[b * 64 + t];
    sv[t] = sk * Wl[t];
    __syncthreads();
    if (t == 0) {
        float s = 0.f;
        for (int i = 0; i < 64; i++) s += sv[i];
        s += bl[0];
        out[0] = 1.f / (1.f + expf(-s));
    }
}

extern "C" void kernel_launch(void* const* d_in, const int* in_sizes, int n_in,
                              void* d_out, int out_size)
{
    const float* x     = (const float*)d_in[0];
    const float* alpha = (const float*)d_in[1];
    const float* W1    = (const float*)d_in[2];
    const float* b1    = (const float*)d_in[3];
    const float* wt1   = (const float*)d_in[4];
    const float* bs1   = (const float*)d_in[5];
    const float* W2    = (const float*)d_in[6];
    const float* b2    = (const float*)d_in[7];
    const float* wt2   = (const float*)d_in[8];
    const float* bs2   = (const float*)d_in[9];
    const float* Wl    = (const float*)d_in[10];
    const float* bl    = (const float*)d_in[11];
    float* out = (float*)d_out;

    dim3 pg(NN / MT, NSPLIT);

    ep_kernel<<<NN / 256, 256>>>(x, alpha);
    // layer 1: weights on the fly, den accumulated
    prep_kernel<7><<<NN / 32, 256>>>(x, W1, b1, wt1);
    pass_kernel<1><<<pg, 256>>>(alpha);
    finalize_kernel<<<NN * DD / 256, 256>>>(bs1);
    // layer 2: weights recomputed on the fly, den reused from layer 1
    prep_kernel<64><<<NN / 32, 256>>>(nullptr, W2, b2, wt2);
    pass_kernel<0><<<pg, 256>>>(alpha);
    // head: finalize2 fused into reduce
    reduce_kernel<<<64, 256>>>(bs2);
    head_kernel<<<1, 64>>>(Wl, bl, out);
}

// round 15
// speedup vs baseline: 1.1556x; 1.1395x over previous
#include <cuda_runtime.h>
#include <cuda_fp16.h>
#include <math.h>
#include <stdint.h>

#define NN 8192
#define DD 64
#define NSPLIT 4
#define MT 128          // rows per CTA
#define JT 128          // j tile
#define JSPAN (NN / NSPLIT)        // 2048 j's per CTA
#define NTILE (JSPAN / JT)         // 16 j-tiles per CTA
#define SGS 136         // padded sG row stride (halves)
#define SGBYTES (64 * SGS * 2)     // one sG buffer in bytes

// ---- static device scratch (no allocation allowed) ----
__device__ float  g_G[NN * DD];            // G = relu(X@W+b)@wt (fp32, row-major)
__device__ __half g_GT[DD * NN];           // G transposed, fp16 (feature-major)
__device__ float  g_V[NN * DD];            // layer-1 output
__device__ float  g_num[NSPLIT * NN * DD]; // numerator partials
__device__ float  g_den[NSPLIT * NN];      // denominator partials (pass1 only)
__device__ __half g_ephe[NN];              // scaled eta (fp16)
__device__ __half g_ephp[NN];              // scaled phi (fp16)
__device__ float  g_part[64 * 64];

#define CP_ASYNC16(dst, src) \
    asm volatile("cp.async.cg.shared.global [%0], [%1], 16;" :: "r"(dst), "l"(src))
#define CP_COMMIT() asm volatile("cp.async.commit_group;" ::: "memory")
#define CP_WAIT(n)  asm volatile("cp.async.wait_group %0;" :: "n"(n) : "memory")

// ============================================================
// ep: scaled fp16 SoA coords.  s = sqrt(alpha*log2e) so that
// 2^(-(de^2+dp^2)) == exp(-alpha*dR^2)
// ============================================================
__global__ void ep_kernel(const float* __restrict__ x, const float* __restrict__ alpha) {
    const float LOG2E = 1.44269504088896340736f;
    float s = sqrtf(alpha[0] * LOG2E);
    int j = blockIdx.x * 256 + threadIdx.x;
    g_ephe[j] = __float2half(x[j * 7 + 1] * s);
    g_ephp[j] = __float2half(x[j * 7 + 2] * s);
}

// ============================================================
// prep v2: G = relu(X@W+b)@wt, weights in SMEM, 4 cols/thread via
// float4 LDS. 16 row-slots x 16 col-groups, 32 rows/CTA, low regs.
// ============================================================
template<int DIN>
__global__ __launch_bounds__(256) void prep_kernel(
    const float* __restrict__ Xext, const float* __restrict__ W,
    const float* __restrict__ b, const float* __restrict__ wt)
{
    __shared__ float sW[DIN * 64];
    __shared__ float swt[64 * 64];
    __shared__ float sx[16][(DIN <= 8) ? 8 : 64];
    __shared__ float sh[16][64];
    __shared__ __half sgt[32][64];

    const int tid = threadIdx.x;
    const int rs = tid >> 4;       // row slot 0..15
    const int cg = tid & 15;       // col group (4 cols)
    const float* X = Xext ? Xext : g_V;
    const int rowbase = blockIdx.x * 32;

    // cooperative weight loads (float4)
    for (int t = tid; t < DIN * 16; t += 256)
        ((float4*)sW)[t] = ((const float4*)W)[t];
    for (int t = tid; t < 64 * 16; t += 256)
        ((float4*)swt)[t] = ((const float4*)wt)[t];
    const float4 bk4 = *(const float4*)&b[cg * 4];
    __syncthreads();

    #pragma unroll
    for (int half = 0; half < 2; half++) {
        const int row = rowbase + half * 16 + rs;
        // load X row into sx
        if (DIN <= 8) {
            if (cg < DIN) sx[rs][cg] = X[row * DIN + cg];
        } else {
            *(float4*)&sx[rs][cg * 4] = *(const float4*)&X[row * DIN + cg * 4];
        }
        __syncthreads();
        // stage 1: h = relu(x @ W + b), 4 cols per thread
        float a0 = bk4.x, a1 = bk4.y, a2 = bk4.z, a3 = bk4.w;
        #pragma unroll
        for (int d = 0; d < DIN; d++) {
            float xv = sx[rs][d];
            float4 w4 = *(const float4*)&sW[d * 64 + cg * 4];
            a0 = fmaf(xv, w4.x, a0); a1 = fmaf(xv, w4.y, a1);
            a2 = fmaf(xv, w4.z, a2); a3 = fmaf(xv, w4.w, a3);
        }
        *(float4*)&sh[rs][cg * 4] = make_float4(fmaxf(a0, 0.f), fmaxf(a1, 0.f),
                                                fmaxf(a2, 0.f), fmaxf(a3, 0.f));
        __syncthreads();
        // stage 2: g = h @ wt, 4 cols per thread
        float g0 = 0.f, g1 = 0.f, g2 = 0.f, g3 = 0.f;
        #pragma unroll
        for (int m = 0; m < 64; m++) {
            float hv = sh[rs][m];
            float4 w4 = *(const float4*)&swt[m * 64 + cg * 4];
            g0 = fmaf(hv, w4.x, g0); g1 = fmaf(hv, w4.y, g1);
            g2 = fmaf(hv, w4.z, g2); g3 = fmaf(hv, w4.w, g3);
        }
        *(float4*)&g_G[row * 64 + cg * 4] = make_float4(g0, g1, g2, g3);
        sgt[half * 16 + rs][cg * 4 + 0] = __float2half(g0);
        sgt[half * 16 + rs][cg * 4 + 1] = __float2half(g1);
        sgt[half * 16 + rs][cg * 4 + 2] = __float2half(g2);
        sgt[half * 16 + rs][cg * 4 + 3] = __float2half(g3);
    }
    __syncthreads();
    // coalesced transposed store: g_GT[k][rowbase..rowbase+31]
    const int kk = tid >> 2, seg = tid & 3;
    __half tmp[8];
    #pragma unroll
    for (int r = 0; r < 8; r++) tmp[r] = sgt[seg * 8 + r][kk];
    *(float4*)(g_GT + kk * NN + rowbase + seg * 8) = *(float4*)tmp;
}

// ============================================================
// wgen: half2-packed weights for a j-pair (two packed ex2 — the
// proven-fastest form). drn = LL - de^2 - dp^2 ; w = 2^(2^drn)
// ============================================================
__device__ __forceinline__ uint32_t wgen(half2 ei, half2 pi, half2 ej, half2 pj,
                                         half2 tps2, half2 LL2) {
    half2 de = __hsub2(ei, ej);
    half2 d  = __hsub2(pi, pj);
    half2 ad = __habs2(d);
    half2 dp = __hmin2(ad, __hsub2(tps2, ad));
    half2 s  = __hfma2(dp, dp, __hmul2(de, de));
    half2 drn = __hsub2(LL2, s);
    uint32_t r;
    asm("{\n\t.reg .b32 t;\n\t"
        "ex2.approx.f16x2 t, %1;\n\t"
        "ex2.approx.f16x2 %0, t;\n\t}"
        : "=r"(r) : "r"(*(uint32_t*)&drn));
    return r;
}

// ============================================================
// pass: S@G on HMMA, cp.async double-buffered G tiles.
// DEN=1 additionally accumulates the softmax denominator via an
// extra MMA against a constant ones-B fragment (layer 1 only).
// ============================================================
template<int DEN>
__global__ __launch_bounds__(256, 3) void pass_kernel(const float* __restrict__ alpha)
{
    __shared__ __half sG[2][64 * SGS];   // [buf][feature][j] padded
    __shared__ __half sEe[2][JT];
    __shared__ __half sEp[2][JT];

    const int tid = threadIdx.x;
    const int warp = tid >> 5, lane = tid & 31;
    const int gid = lane >> 2, tig = lane & 3;
    const int rowtile = blockIdx.x, jsplit = blockIdx.y;
    const int j0base = jsplit * JSPAN;

    const int row0 = rowtile * MT + warp * 16 + gid;

    const float LOG2E = 1.44269504088896340736f;
    const float TWOPI = 6.28318530717958647692f;
    float tps = TWOPI * sqrtf(alpha[0] * LOG2E);
    const half2 tps2 = __half2half2(__float2half(tps));
    const half2 LL2  = __half2half2(__float2half(0.52876637294489770f));
    const half2 ei0_2 = __half2half2(g_ephe[row0]);
    const half2 pi0_2 = __half2half2(g_ephp[row0]);
    const half2 ei1_2 = __half2half2(g_ephe[row0 + 8]);
    const half2 pi1_2 = __half2half2(g_ephp[row0 + 8]);

    // ldmatrix per-lane address offset (halves)
    const int m = lane >> 3;
    const int bro = ((m >> 1) * 8 + (lane & 7)) * SGS + (m & 1) * 8;

    uint32_t sgb, seeb, sepb;
    asm("{ .reg .u64 t; cvta.to.shared.u64 t, %1; cvt.u32.u64 %0, t; }" : "=r"(sgb) : "l"(&sG[0][0]));
    asm("{ .reg .u64 t; cvta.to.shared.u64 t, %1; cvt.u32.u64 %0, t; }" : "=r"(seeb) : "l"(&sEe[0][0]));
    asm("{ .reg .u64 t; cvta.to.shared.u64 t, %1; cvt.u32.u64 %0, t; }" : "=r"(sepb) : "l"(&sEp[0][0]));

    // prefetch lambda: stream tile t into buffer (t&1) via cp.async
    const int pf_f = tid >> 4, pf_c = tid & 15;   // 4 rows of 16B per thread
    auto issue_tile = [&](int t) {
        const int j0 = j0base + t * JT;
        const int buf = t & 1;
        #pragma unroll
        for (int i = 0; i < 4; i++) {
            int f = pf_f + i * 16;
            uint32_t dst = sgb + buf * SGBYTES + (uint32_t)(f * SGS + pf_c * 8) * 2u;
            CP_ASYNC16(dst, g_GT + f * NN + j0 + pf_c * 8);
        }
        if (tid < 16)
            CP_ASYNC16(seeb + buf * (JT * 2) + tid * 16, g_ephe + j0 + tid * 8);
        else if (tid < 32)
            CP_ASYNC16(sepb + buf * (JT * 2) + (tid - 16) * 16, g_ephp + j0 + (tid - 16) * 8);
        CP_COMMIT();
    };

    float acc[8][4];
    #pragma unroll
    for (int nt = 0; nt < 8; nt++)
        #pragma unroll
        for (int q = 0; q < 4; q++) acc[nt][q] = 0.f;
    float accd[4] = {0.f, 0.f, 0.f, 0.f};   // den accumulator (DEN only)

    issue_tile(0);

    for (int t = 0; t < NTILE; t++) {
        const int buf = t & 1;
        if (t + 1 < NTILE) { issue_tile(t + 1); CP_WAIT(1); }
        else               { CP_WAIT(0); }
        __syncthreads();

        const uint32_t sgbuf = sgb + buf * SGBYTES;
        const __half* ee = &sEe[buf][0];
        const __half* pp = &sEp[buf][0];

        #pragma unroll
        for (int ks = 0; ks < 8; ks++) {
            const int jj = ks * 16;
            half2 ej0 = *(const half2*)(ee + jj + tig * 2);
            half2 pj0 = *(const half2*)(pp + jj + tig * 2);
            half2 ej1 = *(const half2*)(ee + jj + 8 + tig * 2);
            half2 pj1 = *(const half2*)(pp + jj + 8 + tig * 2);
            uint32_t af0 = wgen(ei0_2, pi0_2, ej0, pj0, tps2, LL2);
            uint32_t af1 = wgen(ei1_2, pi1_2, ej0, pj0, tps2, LL2);
            uint32_t af2 = wgen(ei0_2, pi0_2, ej1, pj1, tps2, LL2);
            uint32_t af3 = wgen(ei1_2, pi1_2, ej1, pj1, tps2, LL2);
            if (DEN) {
                // den: MMA against constant all-ones B fragment
                asm volatile(
                    "mma.sync.aligned.m16n8k16.row.col.f32.f16.f16.f32 "
                    "{%0,%1,%2,%3}, {%4,%5,%6,%7}, {%8,%8}, {%0,%1,%2,%3};"
                    : "+f"(accd[0]), "+f"(accd[1]), "+f"(accd[2]), "+f"(accd[3])
                    : "r"(af0), "r"(af1), "r"(af2), "r"(af3), "r"(0x3C003C00u));
            }

            // two half-groups of (2 ldmatrix.x4 + 4 MMA) to cap live regs
            #pragma unroll
            for (int h = 0; h < 2; h++) {
                uint32_t bf[4][2];
                #pragma unroll
                for (int q = 0; q < 2; q++) {
                    uint32_t addr = sgbuf + (uint32_t)((h * 2 + q) * 16 * SGS + bro + jj) * 2u;
                    asm volatile("ldmatrix.sync.aligned.m8n8.x4.shared.b16 {%0,%1,%2,%3}, [%4];"
                        : "=r"(bf[2 * q][0]), "=r"(bf[2 * q][1]),
                          "=r"(bf[2 * q + 1][0]), "=r"(bf[2 * q + 1][1])
                        : "r"(addr));
                }
                #pragma unroll
                for (int nt = 0; nt < 4; nt++) {
                    asm volatile(
                        "mma.sync.aligned.m16n8k16.row.col.f32.f16.f16.f32 "
                        "{%0,%1,%2,%3}, {%4,%5,%6,%7}, {%8,%9}, {%0,%1,%2,%3};"
                        : "+f"(acc[h * 4 + nt][0]), "+f"(acc[h * 4 + nt][1]),
                          "+f"(acc[h * 4 + nt][2]), "+f"(acc[h * 4 + nt][3])
                        : "r"(af0), "r"(af1), "r"(af2), "r"(af3),
                          "r"(bf[nt][0]), "r"(bf[nt][1]));
                }
            }
        }
        __syncthreads();
    }

    if (DEN && tig == 0) {
        g_den[jsplit * NN + row0] = accd[0];
        g_den[jsplit * NN + row0 + 8] = accd[2];
    }

    float* np = g_num + (size_t)jsplit * NN * DD;
    #pragma unroll
    for (int nt = 0; nt < 8; nt++) {
        *(float2*)(np + (size_t)row0 * DD + nt * 8 + tig * 2) =
            make_float2(acc[nt][0], acc[nt][1]);
        *(float2*)(np + (size_t)(row0 + 8) * DD + nt * 8 + tig * 2) =
            make_float2(acc[nt][2], acc[nt][3]);
    }
}

// ============================================================
// finalize (layer 1): V = relu(num/den + G + bs)
// ============================================================
__global__ __launch_bounds__(256) void finalize_kernel(const float* __restrict__ bs)
{
    int gid = blockIdx.x * 256 + threadIdx.x;
    int i = gid >> 6;
    float ds = 0.f, ns = 0.f;
    #pragma unroll
    for (int s = 0; s < NSPLIT; s++) {
        ds += g_den[s * NN + i];
        ns += g_num[(size_t)s * NN * DD + gid];
    }
    float v = ns / ds + g_G[gid] + bs[0];
    g_V[gid] = fmaxf(v, 0.f);
}

// ============================================================
// reduce (finalize2 fused): column sums of relu(num/den + G + bs)
// ============================================================
__global__ __launch_bounds__(256) void reduce_kernel(const float* __restrict__ bs)
{
    __shared__ float s[4][64];
    int tid = threadIdx.x;
    int k = tid & 63;
    int rg = tid >> 6;
    int bkt = blockIdx.x;
    float acc = 0.f;
    for (int r = rg; r < 128; r += 4) {
        int row = bkt * 128 + r;
        float ds = 0.f, ns = 0.f;
        #pragma unroll
        for (int sp = 0; sp < NSPLIT; sp++) {
            ds += g_den[sp * NN + row];
            ns += g_num[(size_t)sp * NN * DD + (size_t)row * DD + k];
        }
        float v = ns / ds + g_G[row * 64 + k] + bs[0];
        acc += fmaxf(v, 0.f);
    }
    s[rg][k] = acc;
    __syncthreads();
    if (tid < 64)
        g_part[bkt * 64 + tid] = s[0][tid] + s[1][tid] + s[2][tid] + s[3][tid];
}

__global__ void head_kernel(const float* __restrict__ Wl,
                            const float* __restrict__ bl,
                            float* __restrict__ out)
{
    __shared__ float sv[64];
    int t = threadIdx.x;
    float sk = 0.f;
    for (int b = 0; b < 64; b++) sk += g_part[b * 64 + t];
    sv[t] = sk * Wl[t];
    __syncthreads();
    if (t == 0) {
        float s = 0.f;
        for (int i = 0; i < 64; i++) s += sv[i];
        s += bl[0];
        out[0] = 1.f / (1.f + expf(-s));
    }
}

extern "C" void kernel_launch(void* const* d_in, const int* in_sizes, int n_in,
                              void* d_out, int out_size)
{
    const float* x     = (const float*)d_in[0];
    const float* alpha = (const float*)d_in[1];
    const float* W1    = (const float*)d_in[2];
    const float* b1    = (const float*)d_in[3];
    const float* wt1   = (const float*)d_in[4];
    const float* bs1   = (const float*)d_in[5];
    const float* W2    = (const float*)d_in[6];
    const float* b2    = (const float*)d_in[7];
    const float* wt2   = (const float*)d_in[8];
    const float* bs2   = (const float*)d_in[9];
    const float* Wl    = (const float*)d_in[10];
    const float* bl    = (const float*)d_in[11];
    float* out = (float*)d_out;

    dim3 pg(NN / MT, NSPLIT);

    ep_kernel<<<NN / 256, 256>>>(x, alpha);
    // layer 1: weights on the fly, den accumulated
    prep_kernel<7><<<NN / 32, 256>>>(x, W1, b1, wt1);
    pass_kernel<1><<<pg, 256>>>(alpha);
    finalize_kernel<<<NN * DD / 256, 256>>>(bs1);
    // layer 2: weights recomputed on the fly, den reused from layer 1
    prep_kernel<64><<<NN / 32, 256>>>(nullptr, W2, b2, wt2);
    pass_kernel<0><<<pg, 256>>>(alpha);
    // head: finalize2 fused into reduce
    reduce_kernel<<<64, 256>>>(bs2);
    head_kernel<<<1, 64>>>(Wl, bl, out);
}

// round 16
// speedup vs baseline: 1.2363x; 1.0699x over previous
#include <cuda_runtime.h>
#include <cuda_fp16.h>
#include <math.h>
#include <stdint.h>

#define NN 8192
#define DD 64
#define NSPLIT 4
#define MT 128          // rows per CTA
#define JT 128          // j tile
#define JSPAN (NN / NSPLIT)        // 2048 j's per CTA
#define NTILE (JSPAN / JT)         // 16 j-tiles per CTA
#define SGS 136         // padded sG row stride (halves)
#define SGBYTES (64 * SGS * 2)     // 17408: one sG buffer
#define EPOFF   SGBYTES            // sEe offset within buffer
#define PPOFF   (SGBYTES + 256)    // sEp offset within buffer
#define BUFB    (SGBYTES + 512)    // 17920: full buffer stride
#define SMEM_PASS (3 * BUFB)       // 53760 bytes dynamic smem

// ---- static device scratch (no allocation allowed) ----
__device__ float  g_G[NN * DD];            // G = relu(X@W+b)@wt (fp32, row-major)
__device__ __half g_GT[DD * NN];           // G transposed, fp16 (feature-major)
__device__ float  g_V[NN * DD];            // layer-1 output
__device__ float  g_num[NSPLIT * NN * DD]; // numerator partials
__device__ float  g_den[NSPLIT * NN];      // denominator partials (pass1 only)
__device__ __half g_ephe[NN];              // scaled eta (fp16)
__device__ __half g_ephp[NN];              // scaled phi (fp16)
__device__ float  g_part[64 * 64];

#define CP_ASYNC16(dst, src) \
    asm volatile("cp.async.cg.shared.global [%0], [%1], 16;" :: "r"(dst), "l"(src))
#define CP_COMMIT() asm volatile("cp.async.commit_group;" ::: "memory")
#define CP_WAIT(n)  asm volatile("cp.async.wait_group %0;" :: "n"(n) : "memory")

// ============================================================
// ep: scaled fp16 SoA coords.  s = sqrt(alpha*log2e) so that
// 2^(-(de^2+dp^2)) == exp(-alpha*dR^2)
// ============================================================
__global__ void ep_kernel(const float* __restrict__ x, const float* __restrict__ alpha) {
    const float LOG2E = 1.44269504088896340736f;
    float s = sqrtf(alpha[0] * LOG2E);
    int j = blockIdx.x * 256 + threadIdx.x;
    g_ephe[j] = __float2half(x[j * 7 + 1] * s);
    g_ephp[j] = __float2half(x[j * 7 + 2] * s);
}

// ============================================================
// prep v2: G = relu(X@W+b)@wt, weights in SMEM, 4 cols/thread via
// float4 LDS. 16 row-slots x 16 col-groups, 32 rows/CTA, low regs.
// ============================================================
template<int DIN>
__global__ __launch_bounds__(256) void prep_kernel(
    const float* __restrict__ Xext, const float* __restrict__ W,
    const float* __restrict__ b, const float* __restrict__ wt)
{
    __shared__ float sW[DIN * 64];
    __shared__ float swt[64 * 64];
    __shared__ float sx[16][(DIN <= 8) ? 8 : 64];
    __shared__ float sh[16][64];
    __shared__ __half sgt[32][64];

    const int tid = threadIdx.x;
    const int rs = tid >> 4;       // row slot 0..15
    const int cg = tid & 15;       // col group (4 cols)
    const float* X = Xext ? Xext : g_V;
    const int rowbase = blockIdx.x * 32;

    // cooperative weight loads (float4)
    for (int t = tid; t < DIN * 16; t += 256)
        ((float4*)sW)[t] = ((const float4*)W)[t];
    for (int t = tid; t < 64 * 16; t += 256)
        ((float4*)swt)[t] = ((const float4*)wt)[t];
    const float4 bk4 = *(const float4*)&b[cg * 4];
    __syncthreads();

    #pragma unroll
    for (int half = 0; half < 2; half++) {
        const int row = rowbase + half * 16 + rs;
        // load X row into sx
        if (DIN <= 8) {
            if (cg < DIN) sx[rs][cg] = X[row * DIN + cg];
        } else {
            *(float4*)&sx[rs][cg * 4] = *(const float4*)&X[row * DIN + cg * 4];
        }
        __syncthreads();
        // stage 1: h = relu(x @ W + b), 4 cols per thread
        float a0 = bk4.x, a1 = bk4.y, a2 = bk4.z, a3 = bk4.w;
        #pragma unroll
        for (int d = 0; d < DIN; d++) {
            float xv = sx[rs][d];
            float4 w4 = *(const float4*)&sW[d * 64 + cg * 4];
            a0 = fmaf(xv, w4.x, a0); a1 = fmaf(xv, w4.y, a1);
            a2 = fmaf(xv, w4.z, a2); a3 = fmaf(xv, w4.w, a3);
        }
        *(float4*)&sh[rs][cg * 4] = make_float4(fmaxf(a0, 0.f), fmaxf(a1, 0.f),
                                                fmaxf(a2, 0.f), fmaxf(a3, 0.f));
        __syncthreads();
        // stage 2: g = h @ wt, 4 cols per thread
        float g0 = 0.f, g1 = 0.f, g2 = 0.f, g3 = 0.f;
        #pragma unroll
        for (int m = 0; m < 64; m++) {
            float hv = sh[rs][m];
            float4 w4 = *(const float4*)&swt[m * 64 + cg * 4];
            g0 = fmaf(hv, w4.x, g0); g1 = fmaf(hv, w4.y, g1);
            g2 = fmaf(hv, w4.z, g2); g3 = fmaf(hv, w4.w, g3);
        }
        *(float4*)&g_G[row * 64 + cg * 4] = make_float4(g0, g1, g2, g3);
        sgt[half * 16 + rs][cg * 4 + 0] = __float2half(g0);
        sgt[half * 16 + rs][cg * 4 + 1] = __float2half(g1);
        sgt[half * 16 + rs][cg * 4 + 2] = __float2half(g2);
        sgt[half * 16 + rs][cg * 4 + 3] = __float2half(g3);
    }
    __syncthreads();
    // coalesced transposed store: g_GT[k][rowbase..rowbase+31]
    const int kk = tid >> 2, seg = tid & 3;
    __half tmp[8];
    #pragma unroll
    for (int r = 0; r < 8; r++) tmp[r] = sgt[seg * 8 + r][kk];
    *(float4*)(g_GT + kk * NN + rowbase + seg * 8) = *(float4*)tmp;
}

// ============================================================
// wgen: half2-packed weights for a j-pair (two packed ex2).
// drn = LL - de^2 - dp^2 via fused-negate FMAs; w = 2^(2^drn)
// ============================================================
__device__ __forceinline__ uint32_t wgen(half2 ei, half2 pi, half2 ej, half2 pj,
                                         half2 tps2, half2 LL2) {
    half2 de = __hsub2(ei, ej);
    half2 d  = __hsub2(pi, pj);
    half2 ad = __habs2(d);
    half2 dp = __hmin2(ad, __hsub2(tps2, ad));
    half2 t  = __hfma2(__hneg2(de), de, LL2);
    half2 drn = __hfma2(__hneg2(dp), dp, t);
    uint32_t r;
    asm("{\n\t.reg .b32 t;\n\t"
        "ex2.approx.f16x2 t, %1;\n\t"
        "ex2.approx.f16x2 %0, t;\n\t}"
        : "=r"(r) : "r"(*(uint32_t*)&drn));
    return r;
}

// ============================================================
// pass: S@G on HMMA, 3-stage cp.async pipeline, ONE sync per tile.
// DEN=1 additionally accumulates the softmax denominator via an
// extra MMA against a constant ones-B fragment (layer 1 only).
// ============================================================
template<int DEN>
__global__ __launch_bounds__(256, 3) void pass_kernel(const float* __restrict__ alpha)
{
    extern __shared__ char smem[];

    const int tid = threadIdx.x;
    const int warp = tid >> 5, lane = tid & 31;
    const int gid = lane >> 2, tig = lane & 3;
    const int rowtile = blockIdx.x, jsplit = blockIdx.y;
    const int j0base = jsplit * JSPAN;

    const int row0 = rowtile * MT + warp * 16 + gid;

    const float LOG2E = 1.44269504088896340736f;
    const float TWOPI = 6.28318530717958647692f;
    float tps = TWOPI * sqrtf(alpha[0] * LOG2E);
    const half2 tps2 = __half2half2(__float2half(tps));
    const half2 LL2  = __half2half2(__float2half(0.52876637294489770f));
    const half2 ei0_2 = __half2half2(g_ephe[row0]);
    const half2 pi0_2 = __half2half2(g_ephp[row0]);
    const half2 ei1_2 = __half2half2(g_ephe[row0 + 8]);
    const half2 pi1_2 = __half2half2(g_ephp[row0 + 8]);

    // ldmatrix per-lane address offset (halves)
    const int m = lane >> 3;
    const int bro = ((m >> 1) * 8 + (lane & 7)) * SGS + (m & 1) * 8;

    uint32_t sbase;
    asm("{ .reg .u64 t; cvta.to.shared.u64 t, %1; cvt.u32.u64 %0, t; }" : "=r"(sbase) : "l"(smem));

    // prefetch: stream tile t into buffer (t%3) via cp.async
    const int pf_f = tid >> 4, pf_c = tid & 15;   // 4 rows of 16B per thread
    auto issue_tile = [&](int t) {
        const int j0 = j0base + t * JT;
        const uint32_t bb = sbase + (uint32_t)(t % 3) * BUFB;
        #pragma unroll
        for (int i = 0; i < 4; i++) {
            int f = pf_f + i * 16;
            CP_ASYNC16(bb + (uint32_t)(f * SGS + pf_c * 8) * 2u, g_GT + f * NN + j0 + pf_c * 8);
        }
        if (tid < 16)
            CP_ASYNC16(bb + EPOFF + tid * 16, g_ephe + j0 + tid * 8);
        else if (tid < 32)
            CP_ASYNC16(bb + PPOFF + (tid - 16) * 16, g_ephp + j0 + (tid - 16) * 8);
        CP_COMMIT();
    };

    float acc[8][4];
    #pragma unroll
    for (int nt = 0; nt < 8; nt++)
        #pragma unroll
        for (int q = 0; q < 4; q++) acc[nt][q] = 0.f;
    float accd[4] = {0.f, 0.f, 0.f, 0.f};   // den accumulator (DEN only)

    issue_tile(0);
    issue_tile(1);

    for (int t = 0; t < NTILE; t++) {
        if (t + 1 < NTILE) CP_WAIT(1); else CP_WAIT(0);
        __syncthreads();                         // tile t visible; buf (t+2)%3 free
        if (t + 2 < NTILE) issue_tile(t + 2);

        const uint32_t bb = sbase + (uint32_t)(t % 3) * BUFB;
        const __half* ee = (const __half*)(smem + (t % 3) * BUFB + EPOFF);
        const __half* pp = (const __half*)(smem + (t % 3) * BUFB + PPOFF);

        #pragma unroll
        for (int ks = 0; ks < 8; ks++) {
            const int jj = ks * 16;
            half2 ej0 = *(const half2*)(ee + jj + tig * 2);
            half2 pj0 = *(const half2*)(pp + jj + tig * 2);
            half2 ej1 = *(const half2*)(ee + jj + 8 + tig * 2);
            half2 pj1 = *(const half2*)(pp + jj + 8 + tig * 2);
            uint32_t af0 = wgen(ei0_2, pi0_2, ej0, pj0, tps2, LL2);
            uint32_t af1 = wgen(ei1_2, pi1_2, ej0, pj0, tps2, LL2);
            uint32_t af2 = wgen(ei0_2, pi0_2, ej1, pj1, tps2, LL2);
            uint32_t af3 = wgen(ei1_2, pi1_2, ej1, pj1, tps2, LL2);
            if (DEN) {
                // den: MMA against constant all-ones B fragment
                asm volatile(
                    "mma.sync.aligned.m16n8k16.row.col.f32.f16.f16.f32 "
                    "{%0,%1,%2,%3}, {%4,%5,%6,%7}, {%8,%8}, {%0,%1,%2,%3};"
                    : "+f"(accd[0]), "+f"(accd[1]), "+f"(accd[2]), "+f"(accd[3])
                    : "r"(af0), "r"(af1), "r"(af2), "r"(af3), "r"(0x3C003C00u));
            }

            // two half-groups of (2 ldmatrix.x4 + 4 MMA) to cap live regs
            #pragma unroll
            for (int h = 0; h < 2; h++) {
                uint32_t bf[4][2];
                #pragma unroll
                for (int q = 0; q < 2; q++) {
                    uint32_t addr = bb + (uint32_t)((h * 2 + q) * 16 * SGS + bro + jj) * 2u;
                    asm volatile("ldmatrix.sync.aligned.m8n8.x4.shared.b16 {%0,%1,%2,%3}, [%4];"
                        : "=r"(bf[2 * q][0]), "=r"(bf[2 * q][1]),
                          "=r"(bf[2 * q + 1][0]), "=r"(bf[2 * q + 1][1])
                        : "r"(addr));
                }
                #pragma unroll
                for (int nt = 0; nt < 4; nt++) {
                    asm volatile(
                        "mma.sync.aligned.m16n8k16.row.col.f32.f16.f16.f32 "
                        "{%0,%1,%2,%3}, {%4,%5,%6,%7}, {%8,%9}, {%0,%1,%2,%3};"
                        : "+f"(acc[h * 4 + nt][0]), "+f"(acc[h * 4 + nt][1]),
                          "+f"(acc[h * 4 + nt][2]), "+f"(acc[h * 4 + nt][3])
                        : "r"(af0), "r"(af1), "r"(af2), "r"(af3),
                          "r"(bf[nt][0]), "r"(bf[nt][1]));
                }
            }
        }
    }

    if (DEN && tig == 0) {
        g_den[jsplit * NN + row0] = accd[0];
        g_den[jsplit * NN + row0 + 8] = accd[2];
    }

    float* np = g_num + (size_t)jsplit * NN * DD;
    #pragma unroll
    for (int nt = 0; nt < 8; nt++) {
        *(float2*)(np + (size_t)row0 * DD + nt * 8 + tig * 2) =
            make_float2(acc[nt][0], acc[nt][1]);
        *(float2*)(np + (size_t)(row0 + 8) * DD + nt * 8 + tig * 2) =
            make_float2(acc[nt][2], acc[nt][3]);
    }
}

// ============================================================
// finalize (layer 1): V = relu(num/den + G + bs)
// ============================================================
__global__ __launch_bounds__(256) void finalize_kernel(const float* __restrict__ bs)
{
    int gid = blockIdx.x * 256 + threadIdx.x;
    int i = gid >> 6;
    float ds = 0.f, ns = 0.f;
    #pragma unroll
    for (int s = 0; s < NSPLIT; s++) {
        ds += g_den[s * NN + i];
        ns += g_num[(size_t)s * NN * DD + gid];
    }
    float v = ns / ds + g_G[gid] + bs[0];
    g_V[gid] = fmaxf(v, 0.f);
}

// ============================================================
// reduce (finalize2 fused): column sums of relu(num/den + G + bs)
// ============================================================
__global__ __launch_bounds__(256) void reduce_kernel(const float* __restrict__ bs)
{
    __shared__ float s[4][64];
    int tid = threadIdx.x;
    int k = tid & 63;
    int rg = tid >> 6;
    int bkt = blockIdx.x;
    float acc = 0.f;
    for (int r = rg; r < 128; r += 4) {
        int row = bkt * 128 + r;
        float ds = 0.f, ns = 0.f;
        #pragma unroll
        for (int sp = 0; sp < NSPLIT; sp++) {
            ds += g_den[sp * NN + row];
            ns += g_num[(size_t)sp * NN * DD + (size_t)row * DD + k];
        }
        float v = ns / ds + g_G[row * 64 + k] + bs[0];
        acc += fmaxf(v, 0.f);
    }
    s[rg][k] = acc;
    __syncthreads();
    if (tid < 64)
        g_part[bkt * 64 + tid] = s[0][tid] + s[1][tid] + s[2][tid] + s[3][tid];
}

__global__ void head_kernel(const float* __restrict__ Wl,
                            const float* __restrict__ bl,
                            float* __restrict__ out)
{
    __shared__ float sv[64];
    int t = threadIdx.x;
    float sk = 0.f;
    for (int b = 0; b < 64; b++) sk += g_part[b * 64 + t];
    sv[t] = sk * Wl[t];
    __syncthreads();
    if (t == 0) {
        float s = 0.f;
        for (int i = 0; i < 64; i++) s += sv[i];
        s += bl[0];
        out[0] = 1.f / (1.f + expf(-s));
    }
}

extern "C" void kernel_launch(void* const* d_in, const int* in_sizes, int n_in,
                              void* d_out, int out_size)
{
    const float* x     = (const float*)d_in[0];
    const float* alpha = (const float*)d_in[1];
    const float* W1    = (const float*)d_in[2];
    const float* b1    = (const float*)d_in[3];
    const float* wt1   = (const float*)d_in[4];
    const float* bs1   = (const float*)d_in[5];
    const float* W2    = (const float*)d_in[6];
    const float* b2    = (const float*)d_in[7];
    const float* wt2   = (const float*)d_in[8];
    const float* bs2   = (const float*)d_in[9];
    const float* Wl    = (const float*)d_in[10];
    const float* bl    = (const float*)d_in[11];
    float* out = (float*)d_out;

    cudaFuncSetAttribute(pass_kernel<1>, cudaFuncAttributeMaxDynamicSharedMemorySize, SMEM_PASS);
    cudaFuncSetAttribute(pass_kernel<0>, cudaFuncAttributeMaxDynamicSharedMemorySize, SMEM_PASS);

    dim3 pg(NN / MT, NSPLIT);

    ep_kernel<<<NN / 256, 256>>>(x, alpha);
    // layer 1: weights on the fly, den accumulated
    prep_kernel<7><<<NN / 32, 256>>>(x, W1, b1, wt1);
    pass_kernel<1><<<pg, 256, SMEM_PASS>>>(alpha);
    finalize_kernel<<<NN * DD / 256, 256>>>(bs1);
    // layer 2: weights recomputed on the fly, den reused from layer 1
    prep_kernel<64><<<NN / 32, 256>>>(nullptr, W2, b2, wt2);
    pass_kernel<0><<<pg, 256, SMEM_PASS>>>(alpha);
    // head: finalize2 fused into reduce
    reduce_kernel<<<64, 256>>>(bs2);
    head_kernel<<<1, 64>>>(Wl, bl, out);
}

// round 17
// speedup vs baseline: 1.2416x; 1.0042x over previous
#include <cuda_runtime.h>
#include <cuda_fp16.h>
#include <math.h>
#include <stdint.h>

#define NN 8192
#define DD 64
#define NSPLIT 4
#define MT 128          // rows per CTA
#define JT 128          // j tile
#define JSPAN (NN / NSPLIT)        // 2048 j's per CTA
#define NTILE (JSPAN / JT)         // 16 j-tiles per CTA
#define SGS 136         // padded sG row stride (halves)
#define SGBYTES (64 * SGS * 2)     // 17408: one sG buffer
#define EPOFF   SGBYTES            // sEe offset within buffer
#define PPOFF   (SGBYTES + 256)    // sEp offset within buffer
#define BUFB    (SGBYTES + 512)    // 17920: full buffer stride
#define SMEM_PASS (3 * BUFB)       // 53760 bytes dynamic smem

// ---- static device scratch (no allocation allowed) ----
__device__ float  g_G[NN * DD];            // G = relu(X@W+b)@wt (fp32, row-major)
__device__ __half g_GT[DD * NN];           // G transposed, fp16 (feature-major)
__device__ float  g_num[NSPLIT * NN * DD]; // numerator partials
__device__ float  g_den[NSPLIT * NN];      // denominator partials (pass1 only)
__device__ __half g_ephe[NN];              // scaled eta (fp16)
__device__ __half g_ephp[NN];              // scaled phi (fp16)
__device__ float  g_part[64 * 64];

#define CP_ASYNC16(dst, src) \
    asm volatile("cp.async.cg.shared.global [%0], [%1], 16;" :: "r"(dst), "l"(src))
#define CP_COMMIT() asm volatile("cp.async.commit_group;" ::: "memory")
#define CP_WAIT(n)  asm volatile("cp.async.wait_group %0;" :: "n"(n) : "memory")

// ============================================================
// ep: scaled fp16 SoA coords.  s = sqrt(alpha*log2e) so that
// 2^(-(de^2+dp^2)) == exp(-alpha*dR^2)
// ============================================================
__global__ void ep_kernel(const float* __restrict__ x, const float* __restrict__ alpha) {
    const float LOG2E = 1.44269504088896340736f;
    float s = sqrtf(alpha[0] * LOG2E);
    int j = blockIdx.x * 256 + threadIdx.x;
    g_ephe[j] = __float2half(x[j * 7 + 1] * s);
    g_ephp[j] = __float2half(x[j * 7 + 2] * s);
}

// ============================================================
// prep v2: G = relu(X@W+b)@wt, weights in SMEM, 4 cols/thread.
// FUSE=1: X = relu(num/den + Gprev + bs) computed inline (layer-1
// finalize fused; low-reg since weights live in SMEM).
// ============================================================
template<int DIN, int FUSE>
__global__ __launch_bounds__(256) void prep_kernel(
    const float* __restrict__ Xext, const float* __restrict__ W,
    const float* __restrict__ b, const float* __restrict__ wt,
    const float* __restrict__ bs)
{
    __shared__ float sW[DIN * 64];
    __shared__ float swt[64 * 64];
    __shared__ float sx[16][(DIN <= 8) ? 8 : 64];
    __shared__ float sh[16][64];
    __shared__ __half sgt[32][64];

    const int tid = threadIdx.x;
    const int rs = tid >> 4;       // row slot 0..15
    const int cg = tid & 15;       // col group (4 cols)
    const int rowbase = blockIdx.x * 32;

    // cooperative weight loads (float4)
    for (int t = tid; t < DIN * 16; t += 256)
        ((float4*)sW)[t] = ((const float4*)W)[t];
    for (int t = tid; t < 64 * 16; t += 256)
        ((float4*)swt)[t] = ((const float4*)wt)[t];
    const float4 bk4 = *(const float4*)&b[cg * 4];
    const float bsv = FUSE ? bs[0] : 0.f;
    __syncthreads();

    #pragma unroll
    for (int half = 0; half < 2; half++) {
        const int row = rowbase + half * 16 + rs;
        // load X row into sx
        if (FUSE) {
            // fused finalize of layer 1: relu(num/den + G + bs)
            float ds = 0.f;
            #pragma unroll
            for (int sp = 0; sp < NSPLIT; sp++) ds += g_den[sp * NN + row];
            float4 nsum = make_float4(0.f, 0.f, 0.f, 0.f);
            #pragma unroll
            for (int sp = 0; sp < NSPLIT; sp++) {
                float4 nv = *(const float4*)&g_num[(size_t)sp * NN * DD + (size_t)row * DD + cg * 4];
                nsum.x += nv.x; nsum.y += nv.y; nsum.z += nv.z; nsum.w += nv.w;
            }
            float4 gv = *(const float4*)&g_G[row * 64 + cg * 4];
            float inv = 1.f / ds;
            sx[rs][cg * 4 + 0] = fmaxf(fmaf(nsum.x, inv, gv.x + bsv), 0.f);
            sx[rs][cg * 4 + 1] = fmaxf(fmaf(nsum.y, inv, gv.y + bsv), 0.f);
            sx[rs][cg * 4 + 2] = fmaxf(fmaf(nsum.z, inv, gv.z + bsv), 0.f);
            sx[rs][cg * 4 + 3] = fmaxf(fmaf(nsum.w, inv, gv.w + bsv), 0.f);
        } else if (DIN <= 8) {
            if (cg < DIN) sx[rs][cg] = Xext[row * DIN + cg];
        } else {
            *(float4*)&sx[rs][cg * 4] = *(const float4*)&Xext[row * DIN + cg * 4];
        }
        __syncthreads();
        // stage 1: h = relu(x @ W + b), 4 cols per thread
        float a0 = bk4.x, a1 = bk4.y, a2 = bk4.z, a3 = bk4.w;
        #pragma unroll
        for (int d = 0; d < DIN; d++) {
            float xv = sx[rs][d];
            float4 w4 = *(const float4*)&sW[d * 64 + cg * 4];
            a0 = fmaf(xv, w4.x, a0); a1 = fmaf(xv, w4.y, a1);
            a2 = fmaf(xv, w4.z, a2); a3 = fmaf(xv, w4.w, a3);
        }
        *(float4*)&sh[rs][cg * 4] = make_float4(fmaxf(a0, 0.f), fmaxf(a1, 0.f),
                                                fmaxf(a2, 0.f), fmaxf(a3, 0.f));
        __syncthreads();
        // stage 2: g = h @ wt, 4 cols per thread
        float g0 = 0.f, g1 = 0.f, g2 = 0.f, g3 = 0.f;
        #pragma unroll
        for (int m = 0; m < 64; m++) {
            float hv = sh[rs][m];
            float4 w4 = *(const float4*)&swt[m * 64 + cg * 4];
            g0 = fmaf(hv, w4.x, g0); g1 = fmaf(hv, w4.y, g1);
            g2 = fmaf(hv, w4.z, g2); g3 = fmaf(hv, w4.w, g3);
        }
        *(float4*)&g_G[row * 64 + cg * 4] = make_float4(g0, g1, g2, g3);
        sgt[half * 16 + rs][cg * 4 + 0] = __float2half(g0);
        sgt[half * 16 + rs][cg * 4 + 1] = __float2half(g1);
        sgt[half * 16 + rs][cg * 4 + 2] = __float2half(g2);
        sgt[half * 16 + rs][cg * 4 + 3] = __float2half(g3);
    }
    __syncthreads();
    // coalesced transposed store: g_GT[k][rowbase..rowbase+31]
    const int kk = tid >> 2, seg = tid & 3;
    __half tmp[8];
    #pragma unroll
    for (int r = 0; r < 8; r++) tmp[r] = sgt[seg * 8 + r][kk];
    *(float4*)(g_GT + kk * NN + rowbase + seg * 8) = *(float4*)tmp;
}

// ============================================================
// wgen: half2-packed weights for a j-pair (two packed ex2).
// drn = LL - de^2 - dp^2 via fused-negate FMAs; w = 2^(2^drn)
// ============================================================
__device__ __forceinline__ uint32_t wgen(half2 ei, half2 pi, half2 ej, half2 pj,
                                         half2 tps2, half2 LL2) {
    half2 de = __hsub2(ei, ej);
    half2 d  = __hsub2(pi, pj);
    half2 ad = __habs2(d);
    half2 dp = __hmin2(ad, __hsub2(tps2, ad));
    half2 t  = __hfma2(__hneg2(de), de, LL2);
    half2 drn = __hfma2(__hneg2(dp), dp, t);
    uint32_t r;
    asm("{\n\t.reg .b32 t;\n\t"
        "ex2.approx.f16x2 t, %1;\n\t"
        "ex2.approx.f16x2 %0, t;\n\t}"
        : "=r"(r) : "r"(*(uint32_t*)&drn));
    return r;
}

// ============================================================
// pass: S@G on HMMA, 3-stage cp.async pipeline, ONE sync per tile.
// DEN=1 additionally accumulates the softmax denominator via an
// extra MMA against a constant ones-B fragment (layer 1 only).
// ============================================================
template<int DEN>
__global__ __launch_bounds__(256, 3) void pass_kernel(const float* __restrict__ alpha)
{
    extern __shared__ char smem[];

    const int tid = threadIdx.x;
    const int warp = tid >> 5, lane = tid & 31;
    const int gid = lane >> 2, tig = lane & 3;
    const int rowtile = blockIdx.x, jsplit = blockIdx.y;
    const int j0base = jsplit * JSPAN;

    const int row0 = rowtile * MT + warp * 16 + gid;

    const float LOG2E = 1.44269504088896340736f;
    const float TWOPI = 6.28318530717958647692f;
    float tps = TWOPI * sqrtf(alpha[0] * LOG2E);
    const half2 tps2 = __half2half2(__float2half(tps));
    const half2 LL2  = __half2half2(__float2half(0.52876637294489770f));
    const half2 ei0_2 = __half2half2(g_ephe[row0]);
    const half2 pi0_2 = __half2half2(g_ephp[row0]);
    const half2 ei1_2 = __half2half2(g_ephe[row0 + 8]);
    const half2 pi1_2 = __half2half2(g_ephp[row0 + 8]);

    // ldmatrix per-lane address offset (halves)
    const int m = lane >> 3;
    const int bro = ((m >> 1) * 8 + (lane & 7)) * SGS + (m & 1) * 8;

    uint32_t sbase;
    asm("{ .reg .u64 t; cvta.to.shared.u64 t, %1; cvt.u32.u64 %0, t; }" : "=r"(sbase) : "l"(smem));

    // prefetch: stream tile t into buffer (t%3) via cp.async
    const int pf_f = tid >> 4, pf_c = tid & 15;   // 4 rows of 16B per thread
    auto issue_tile = [&](int t) {
        const int j0 = j0base + t * JT;
        const uint32_t bb = sbase + (uint32_t)(t % 3) * BUFB;
        #pragma unroll
        for (int i = 0; i < 4; i++) {
            int f = pf_f + i * 16;
            CP_ASYNC16(bb + (uint32_t)(f * SGS + pf_c * 8) * 2u, g_GT + f * NN + j0 + pf_c * 8);
        }
        if (tid < 16)
            CP_ASYNC16(bb + EPOFF + tid * 16, g_ephe + j0 + tid * 8);
        else if (tid < 32)
            CP_ASYNC16(bb + PPOFF + (tid - 16) * 16, g_ephp + j0 + (tid - 16) * 8);
        CP_COMMIT();
    };

    float acc[8][4];
    #pragma unroll
    for (int nt = 0; nt < 8; nt++)
        #pragma unroll
        for (int q = 0; q < 4; q++) acc[nt][q] = 0.f;
    float accd[4] = {0.f, 0.f, 0.f, 0.f};   // den accumulator (DEN only)

    issue_tile(0);
    issue_tile(1);

    for (int t = 0; t < NTILE; t++) {
        if (t + 1 < NTILE) CP_WAIT(1); else CP_WAIT(0);
        __syncthreads();                         // tile t visible; buf (t+2)%3 free
        if (t + 2 < NTILE) issue_tile(t + 2);

        const uint32_t bb = sbase + (uint32_t)(t % 3) * BUFB;
        const __half* ee = (const __half*)(smem + (t % 3) * BUFB + EPOFF);
        const __half* pp = (const __half*)(smem + (t % 3) * BUFB + PPOFF);

        #pragma unroll
        for (int ks = 0; ks < 8; ks++) {
            const int jj = ks * 16;
            half2 ej0 = *(const half2*)(ee + jj + tig * 2);
            half2 pj0 = *(const half2*)(pp + jj + tig * 2);
            half2 ej1 = *(const half2*)(ee + jj + 8 + tig * 2);
            half2 pj1 = *(const half2*)(pp + jj + 8 + tig * 2);
            uint32_t af0 = wgen(ei0_2, pi0_2, ej0, pj0, tps2, LL2);
            uint32_t af1 = wgen(ei1_2, pi1_2, ej0, pj0, tps2, LL2);
            uint32_t af2 = wgen(ei0_2, pi0_2, ej1, pj1, tps2, LL2);
            uint32_t af3 = wgen(ei1_2, pi1_2, ej1, pj1, tps2, LL2);
            if (DEN) {
                // den: MMA against constant all-ones B fragment
                asm volatile(
                    "mma.sync.aligned.m16n8k16.row.col.f32.f16.f16.f32 "
                    "{%0,%1,%2,%3}, {%4,%5,%6,%7}, {%8,%8}, {%0,%1,%2,%3};"
                    : "+f"(accd[0]), "+f"(accd[1]), "+f"(accd[2]), "+f"(accd[3])
                    : "r"(af0), "r"(af1), "r"(af2), "r"(af3), "r"(0x3C003C00u));
            }

            // two half-groups of (2 ldmatrix.x4 + 4 MMA) to cap live regs
            #pragma unroll
            for (int h = 0; h < 2; h++) {
                uint32_t bf[4][2];
                #pragma unroll
                for (int q = 0; q < 2; q++) {
                    uint32_t addr = bb + (uint32_t)((h * 2 + q) * 16 * SGS + bro + jj) * 2u;
                    asm volatile("ldmatrix.sync.aligned.m8n8.x4.shared.b16 {%0,%1,%2,%3}, [%4];"
                        : "=r"(bf[2 * q][0]), "=r"(bf[2 * q][1]),
                          "=r"(bf[2 * q + 1][0]), "=r"(bf[2 * q + 1][1])
                        : "r"(addr));
                }
                #pragma unroll
                for (int nt = 0; nt < 4; nt++) {
                    asm volatile(
                        "mma.sync.aligned.m16n8k16.row.col.f32.f16.f16.f32 "
                        "{%0,%1,%2,%3}, {%4,%5,%6,%7}, {%8,%9}, {%0,%1,%2,%3};"
                        : "+f"(acc[h * 4 + nt][0]), "+f"(acc[h * 4 + nt][1]),
                          "+f"(acc[h * 4 + nt][2]), "+f"(acc[h * 4 + nt][3])
                        : "r"(af0), "r"(af1), "r"(af2), "r"(af3),
                          "r"(bf[nt][0]), "r"(bf[nt][1]));
                }
            }
        }
    }

    if (DEN && tig == 0) {
        g_den[jsplit * NN + row0] = accd[0];
        g_den[jsplit * NN + row0 + 8] = accd[2];
    }

    float* np = g_num + (size_t)jsplit * NN * DD;
    #pragma unroll
    for (int nt = 0; nt < 8; nt++) {
        *(float2*)(np + (size_t)row0 * DD + nt * 8 + tig * 2) =
            make_float2(acc[nt][0], acc[nt][1]);
        *(float2*)(np + (size_t)(row0 + 8) * DD + nt * 8 + tig * 2) =
            make_float2(acc[nt][2], acc[nt][3]);
    }
}

// ============================================================
// reduce (finalize2 fused): column sums of relu(num/den + G + bs)
// ============================================================
__global__ __launch_bounds__(256) void reduce_kernel(const float* __restrict__ bs)
{
    __shared__ float s[4][64];
    int tid = threadIdx.x;
    int k = tid & 63;
    int rg = tid >> 6;
    int bkt = blockIdx.x;
    float acc = 0.f;
    for (int r = rg; r < 128; r += 4) {
        int row = bkt * 128 + r;
        float ds = 0.f, ns = 0.f;
        #pragma unroll
        for (int sp = 0; sp < NSPLIT; sp++) {
            ds += g_den[sp * NN + row];
            ns += g_num[(size_t)sp * NN * DD + (size_t)row * DD + k];
        }
        float v = ns / ds + g_G[row * 64 + k] + bs[0];
        acc += fmaxf(v, 0.f);
    }
    s[rg][k] = acc;
    __syncthreads();
    if (tid < 64)
        g_part[bkt * 64 + tid] = s[0][tid] + s[1][tid] + s[2][tid] + s[3][tid];
}

__global__ void head_kernel(const float* __restrict__ Wl,
                            const float* __restrict__ bl,
                            float* __restrict__ out)
{
    __shared__ float sv[64];
    int t = threadIdx.x;
    float sk = 0.f;
    for (int b = 0; b < 64; b++) sk += g_part[b * 64 + t];
    sv[t] = sk * Wl[t];
    __syncthreads();
    if (t == 0) {
        float s = 0.f;
        for (int i = 0; i < 64; i++) s += sv[i];
        s += bl[0];
        out[0] = 1.f / (1.f + expf(-s));
    }
}

extern "C" void kernel_launch(void* const* d_in, const int* in_sizes, int n_in,
                              void* d_out, int out_size)
{
    const float* x     = (const float*)d_in[0];
    const float* alpha = (const float*)d_in[1];
    const float* W1    = (const float*)d_in[2];
    const float* b1    = (const float*)d_in[3];
    const float* wt1   = (const float*)d_in[4];
    const float* bs1   = (const float*)d_in[5];
    const float* W2    = (const float*)d_in[6];
    const float* b2    = (const float*)d_in[7];
    const float* wt2   = (const float*)d_in[8];
    const float* bs2   = (const float*)d_in[9];
    const float* Wl    = (const float*)d_in[10];
    const float* bl    = (const float*)d_in[11];
    float* out = (float*)d_out;

    cudaFuncSetAttribute(pass_kernel<1>, cudaFuncAttributeMaxDynamicSharedMemorySize, SMEM_PASS);
    cudaFuncSetAttribute(pass_kernel<0>, cudaFuncAttributeMaxDynamicSharedMemorySize, SMEM_PASS);

    dim3 pg(NN / MT, NSPLIT);

    ep_kernel<<<NN / 256, 256>>>(x, alpha);
    // layer 1: weights on the fly, den accumulated
    prep_kernel<7, 0><<<NN / 32, 256>>>(x, W1, b1, wt1, nullptr);
    pass_kernel<1><<<pg, 256, SMEM_PASS>>>(alpha);
    // layer 2: finalize1 fused into prep2 (low-reg prep v2)
    prep_kernel<64, 1><<<NN / 32, 256>>>(nullptr, W2, b2, wt2, bs1);
    pass_kernel<0><<<pg, 256, SMEM_PASS>>>(alpha);
    // head: finalize2 fused into reduce
    reduce_kernel<<<64, 256>>>(bs2);
    head_kernel<<<1, 64>>>(Wl, bl, out);
}